// round 11
// baseline (speedup 1.0000x reference)
#include <cuda_runtime.h>
#include <cuda_bf16.h>
#include <math.h>

#define Bn   8
#define Hn   56
#define Wn   56
#define Cn   192
#define NWIN 1568
#define IND  3072
#define HID  256
#define NCL  256
#define PIX  (Bn*Hn*Wn)

#define OUT_ELEMS   (PIX*Cn)
#define CL_ELEMS    (NWIN*NCL)
#define TOTAL_ELEMS (OUT_ELEMS + CL_ELEMS + NWIN)

#define LN_BLOCKS   (PIX/8)      // 3136
#define W1_TILES    (96*8)       // 768
#define W2_TILES    (6*96)       // 576
#define MEGA_BLOCKS (LN_BLOCKS + NCL + W1_TILES + W2_TILES)

// ---------------- scratch ---------------------------------------------------
__device__ __nv_bfloat16 g_A[NWIN*IND];
__device__ __nv_bfloat16 g_W1t[HID*IND];     // [n][k]
__device__ __nv_bfloat16 g_W2t[IND*Cn];      // [n][k]
__device__ float         g_tmp[2][NWIN*HID];
__device__ __nv_bfloat16 g_logB[NWIN*Cn];
__device__ unsigned      g_pos[NCL*8];
__device__ unsigned      g_neg[NCL*8];
__device__ float         g_cl_fallback[NWIN*NCL];
__device__ float         g_sum_fallback[NWIN];

__device__ __forceinline__ float sigmoidf_(float x) { return 1.f / (1.f + expf(-x)); }

__device__ __forceinline__ void mma_bf16(float* d,
    unsigned a0, unsigned a1, unsigned a2, unsigned a3,
    unsigned b0, unsigned b1)
{
    asm volatile(
        "mma.sync.aligned.m16n8k16.row.col.f32.bf16.bf16.f32 "
        "{%0,%1,%2,%3},{%4,%5,%6,%7},{%8,%9},{%0,%1,%2,%3};\n"
        : "+f"(d[0]), "+f"(d[1]), "+f"(d[2]), "+f"(d[3])
        : "r"(a0), "r"(a1), "r"(a2), "r"(a3), "r"(b0), "r"(b1));
}

__device__ __forceinline__ void cp_async16(void* smem, const void* gmem)
{
    unsigned s = (unsigned)__cvta_generic_to_shared(smem);
    asm volatile("cp.async.cg.shared.global [%0], [%1], 16;\n" :: "r"(s), "l"(gmem));
}
#define CP_COMMIT()  asm volatile("cp.async.commit_group;\n" ::: "memory")
#define CP_WAIT(N)   asm volatile("cp.async.wait_group %0;\n" :: "n"(N) : "memory")

// ---------------- K1: LN+roll+partition | inc masks | weight convert -------
__global__ __launch_bounds__(256) void mega_pre_kernel(
    const float* __restrict__ x, const float* __restrict__ gamma,
    const float* __restrict__ beta, const float* __restrict__ inc_w,
    const float* __restrict__ W1, const float* __restrict__ W2)
{
    __shared__ float tile[32][33];
    int bid = blockIdx.x;
    if (bid < LN_BLOCKS) {
        int warp = threadIdx.x >> 5;
        int lane = threadIdx.x & 31;
        int p = bid * 8 + warp;
        int b   = p / (Hn*Wn);
        int rem = p % (Hn*Wn);
        int h = rem / Wn, w = rem % Wn;
        int sh = (h + 2) % Hn, sw = (w + 2) % Wn;
        const float* src = x + ((size_t)(b*Hn + sh)*Wn + sw)*Cn;

        float v[6], s = 0.f, s2 = 0.f;
        #pragma unroll
        for (int k = 0; k < 6; k++) { v[k] = src[lane + 32*k]; s += v[k]; s2 += v[k]*v[k]; }
        #pragma unroll
        for (int o = 16; o > 0; o >>= 1) {
            s  += __shfl_xor_sync(0xffffffffu, s,  o);
            s2 += __shfl_xor_sync(0xffffffffu, s2, o);
        }
        float mean = s * (1.f/Cn);
        float var  = s2 * (1.f/Cn) - mean*mean;
        float inv  = rsqrtf(var + 1e-5f);

        int hb = h >> 2, i = h & 3, wb = w >> 2, j = w & 3;
        int row = (b*14 + hb)*14 + wb;
        __nv_bfloat16* dst = g_A + (size_t)row*IND + (i*4 + j)*Cn;
        #pragma unroll
        for (int k = 0; k < 6; k++) {
            int c = lane + 32*k;
            dst[c] = __float2bfloat16((v[k] - mean)*inv*gamma[c] + beta[c]);
        }
        return;
    }
    bid -= LN_BLOCKS;
    if (bid < NCL) {
        int t = threadIdx.x;
        unsigned pb = __ballot_sync(0xffffffffu, inc_w[(size_t)bid*512 + t]       > 0.f);
        unsigned nb = __ballot_sync(0xffffffffu, inc_w[(size_t)bid*512 + 256 + t] > 0.f);
        if ((t & 31) == 0) {
            g_pos[bid*8 + (t >> 5)] = pb;
            g_neg[bid*8 + (t >> 5)] = nb;
        }
        return;
    }
    bid -= NCL;
    int tx = threadIdx.x & 31, ty = threadIdx.x >> 5;
    if (bid < W1_TILES) {
        int bi = bid >> 3, bj = bid & 7;
        int r0 = bi*32, c0 = bj*32;
        #pragma unroll
        for (int i = 0; i < 4; i++)
            tile[ty + 8*i][tx] = W1[(size_t)(r0 + ty + 8*i)*HID + c0 + tx];
        __syncthreads();
        #pragma unroll
        for (int i = 0; i < 4; i++)
            g_W1t[(size_t)(c0 + ty + 8*i)*IND + r0 + tx] =
                __float2bfloat16(tile[tx][ty + 8*i]);
    } else {
        bid -= W1_TILES;
        int bi = bid / 96, bj = bid % 96;
        int r0 = bi*32, c0 = bj*32;
        #pragma unroll
        for (int i = 0; i < 4; i++)
            tile[ty + 8*i][tx] = W2[(size_t)(r0 + ty + 8*i)*IND + c0 + tx];
        __syncthreads();
        #pragma unroll
        for (int i = 0; i < 4; i++)
            g_W2t[(size_t)(c0 + ty + 8*i)*Cn + r0 + tx] =
                __float2bfloat16(tile[tx][ty + 8*i]);
    }
}

// ---------------- K2: bf16 GEMM1 split-K, cp.async 4-stage -----------------
// M=1568 N=256 K=1536/z; CTA 64x64; K-chunk 32; 8 warps (2x4), warp 32x16
#define G1_NCHUNK ((IND/2)/32)   // 48
__global__ __launch_bounds__(256) void gemm1_tc()
{
    __shared__ __nv_bfloat16 As[4][64*40];
    __shared__ __nv_bfloat16 Bs[4][64*40];
    const int tid  = threadIdx.x;
    const int warp = tid >> 5, lane = tid & 31;
    const int gid = lane >> 2, tig = lane & 3;
    const int wm = warp >> 2, wn = warp & 3;
    const int row0 = blockIdx.y * 64;
    const int col0 = blockIdx.x * 64;
    const int kbase = blockIdx.z * (IND/2);

    const int lr = tid >> 2;           // 0..63
    const int lc = (tid & 3) * 8;      // bf16 offset within chunk row
    int arow = row0 + lr; if (arow > NWIN-1) arow = NWIN-1;
    const int brow = col0 + lr;

    float acc[2][2][4] = {};

    const __nv_bfloat16* gA = g_A   + (size_t)arow*IND + kbase + lc;
    const __nv_bfloat16* gB = g_W1t + (size_t)brow*IND + kbase + lc;
    __nv_bfloat16* sA = &As[0][lr*40 + lc] - 0;   // stage stride = 64*40
    __nv_bfloat16* sB = &Bs[0][lr*40 + lc] - 0;

    #pragma unroll
    for (int st = 0; st < 3; st++) {
        cp_async16(sA + st*(64*40), gA + st*32);
        cp_async16(sB + st*(64*40), gB + st*32);
        CP_COMMIT();
    }

    for (int kc = 0; kc < G1_NCHUNK; kc++) {
        int rem = G1_NCHUNK - kc;
        if (rem >= 3)      CP_WAIT(2);
        else if (rem == 2) CP_WAIT(1);
        else               CP_WAIT(0);
        __syncthreads();
        if (kc + 3 < G1_NCHUNK) {
            int st = (kc + 3) & 3;
            cp_async16(sA + st*(64*40), gA + (kc+3)*32);
            cp_async16(sB + st*(64*40), gB + (kc+3)*32);
            CP_COMMIT();
        }
        const unsigned* Aw = (const unsigned*)As[kc & 3];
        const unsigned* Bw = (const unsigned*)Bs[kc & 3];
        #pragma unroll
        for (int ks = 0; ks < 2; ks++) {
            int kw = ks*8;
            unsigned a[2][4], bfr[2][2];
            #pragma unroll
            for (int mt = 0; mt < 2; mt++) {
                int base = (wm*32 + mt*16 + gid)*20 + kw + tig;
                a[mt][0] = Aw[base];
                a[mt][1] = Aw[base + 160];
                a[mt][2] = Aw[base + 4];
                a[mt][3] = Aw[base + 164];
            }
            #pragma unroll
            for (int nt = 0; nt < 2; nt++) {
                int bb = (wn*16 + nt*8 + gid)*20 + kw + tig;
                bfr[nt][0] = Bw[bb];
                bfr[nt][1] = Bw[bb + 4];
            }
            #pragma unroll
            for (int mt = 0; mt < 2; mt++)
                #pragma unroll
                for (int nt = 0; nt < 2; nt++)
                    mma_bf16(acc[mt][nt], a[mt][0], a[mt][1], a[mt][2], a[mt][3],
                             bfr[nt][0], bfr[nt][1]);
        }
    }

    float* dst = g_tmp[blockIdx.z];
    #pragma unroll
    for (int mt = 0; mt < 2; mt++)
        #pragma unroll
        for (int nt = 0; nt < 2; nt++)
            #pragma unroll
            for (int e = 0; e < 4; e++) {
                int r   = row0 + wm*32 + mt*16 + gid + (e >= 2 ? 8 : 0);
                int col = col0 + wn*16 + nt*8 + 2*tig + (e & 1);
                if (r < NWIN)
                    dst[(size_t)r*HID + col] = acc[mt][nt][e];
            }
}

// ---------------- K3: bits + clauses + summary + logits (4 rows) -----------
__global__ __launch_bounds__(256) void clause4_kernel(
    const float* __restrict__ b1, const float* __restrict__ vote_w,
    float* __restrict__ clauses_out, float* __restrict__ summary_out)
{
    int t = threadIdx.x;
    int row0 = blockIdx.x * 4;
    __shared__ unsigned s_bits[4][8];
    __shared__ int      s_nfire[4];
    __shared__ int      s_tot[4];
    __shared__ unsigned short s_list[4][NCL];

    if (clauses_out == nullptr) clauses_out = g_cl_fallback;
    if (summary_out == nullptr) summary_out = g_sum_fallback;

    if (t < 4) { s_nfire[t] = 0; s_tot[t] = 0; }
    float bias = b1[t];
    #pragma unroll
    for (int r = 0; r < 4; r++) {
        size_t i = (size_t)(row0 + r)*HID + t;
        float pre = g_tmp[0][i] + g_tmp[1][i] + bias;
        unsigned bb = __ballot_sync(0xffffffffu, pre > 0.f);
        if ((t & 31) == 0) s_bits[r][t >> 5] = bb;
    }
    __syncthreads();

    uint4 p0 = *(const uint4*)&g_pos[t*8];
    uint4 p1 = *(const uint4*)&g_pos[t*8 + 4];
    uint4 n0 = *(const uint4*)&g_neg[t*8];
    uint4 n1 = *(const uint4*)&g_neg[t*8 + 4];

    #pragma unroll
    for (int r = 0; r < 4; r++) {
        unsigned b0_ = s_bits[r][0], b1_ = s_bits[r][1], b2_ = s_bits[r][2], b3_ = s_bits[r][3];
        unsigned b4_ = s_bits[r][4], b5_ = s_bits[r][5], b6_ = s_bits[r][6], b7_ = s_bits[r][7];
        unsigned viol = 0;
        viol |= (p0.x & ~b0_) | (n0.x & b0_);
        viol |= (p0.y & ~b1_) | (n0.y & b1_);
        viol |= (p0.z & ~b2_) | (n0.z & b2_);
        viol |= (p0.w & ~b3_) | (n0.w & b3_);
        viol |= (p1.x & ~b4_) | (n1.x & b4_);
        viol |= (p1.y & ~b5_) | (n1.y & b5_);
        viol |= (p1.z & ~b6_) | (n1.z & b6_);
        viol |= (p1.w & ~b7_) | (n1.w & b7_);
        bool fire = (viol == 0);

        clauses_out[(size_t)(row0 + r)*NCL + t] = fire ? 1.f : 0.f;
        unsigned fb = __ballot_sync(0xffffffffu, fire);
        if ((t & 31) == 0 && fb) atomicAdd(&s_tot[r], __popc(fb));
        if (fire) { int idx = atomicAdd(&s_nfire[r], 1); s_list[r][idx] = (unsigned short)t; }
    }
    __syncthreads();

    if (t < 4) summary_out[row0 + t] = s_tot[t] * (1.f/256.f);

    if (t < Cn) {
        #pragma unroll
        for (int r = 0; r < 4; r++) {
            float acc = 0.f;
            int nf = s_nfire[r];
            for (int i = 0; i < nf; i++)
                acc += vote_w[(size_t)s_list[r][i]*Cn + t];
            g_logB[(size_t)(row0 + r)*Cn + t] = __float2bfloat16(acc * 0.0625f);
        }
    }
}

// ---------------- K4: bf16 GEMM3 + fused epilogue, cp.async ----------------
// M=1568 N=3072 K=192; CTA 64x64; K-chunk 32 (6 chunks)
#define G3_NCHUNK (Cn/32)   // 6
__global__ __launch_bounds__(256) void gemm3_tc(
    const float* __restrict__ x, const float* __restrict__ b2,
    const float* __restrict__ gate, float* __restrict__ out)
{
    __shared__ __nv_bfloat16 As[4][64*40];
    __shared__ __nv_bfloat16 Bs[4][64*40];
    const int tid  = threadIdx.x;
    const int warp = tid >> 5, lane = tid & 31;
    const int gid = lane >> 2, tig = lane & 3;
    const int wm = warp >> 2, wn = warp & 3;
    const int row0 = blockIdx.y * 64;
    const int col0 = blockIdx.x * 64;

    const int lr = tid >> 2;
    const int lc = (tid & 3) * 8;
    int arow = row0 + lr; if (arow > NWIN-1) arow = NWIN-1;
    const int brow = col0 + lr;

    float acc[2][2][4] = {};

    const __nv_bfloat16* gA = g_logB + (size_t)arow*Cn + lc;
    const __nv_bfloat16* gB = g_W2t  + (size_t)brow*Cn + lc;
    __nv_bfloat16* sA = &As[0][lr*40 + lc];
    __nv_bfloat16* sB = &Bs[0][lr*40 + lc];

    #pragma unroll
    for (int st = 0; st < 3; st++) {
        cp_async16(sA + st*(64*40), gA + st*32);
        cp_async16(sB + st*(64*40), gB + st*32);
        CP_COMMIT();
    }

    for (int kc = 0; kc < G3_NCHUNK; kc++) {
        int rem = G3_NCHUNK - kc;
        if (rem >= 3)      CP_WAIT(2);
        else if (rem == 2) CP_WAIT(1);
        else               CP_WAIT(0);
        __syncthreads();
        if (kc + 3 < G3_NCHUNK) {
            int st = (kc + 3) & 3;
            cp_async16(sA + st*(64*40), gA + (kc+3)*32);
            cp_async16(sB + st*(64*40), gB + (kc+3)*32);
            CP_COMMIT();
        }
        const unsigned* Aw = (const unsigned*)As[kc & 3];
        const unsigned* Bw = (const unsigned*)Bs[kc & 3];
        #pragma unroll
        for (int ks = 0; ks < 2; ks++) {
            int kw = ks*8;
            unsigned a[2][4], bfr[2][2];
            #pragma unroll
            for (int mt = 0; mt < 2; mt++) {
                int base = (wm*32 + mt*16 + gid)*20 + kw + tig;
                a[mt][0] = Aw[base];
                a[mt][1] = Aw[base + 160];
                a[mt][2] = Aw[base + 4];
                a[mt][3] = Aw[base + 164];
            }
            #pragma unroll
            for (int nt = 0; nt < 2; nt++) {
                int bb = (wn*16 + nt*8 + gid)*20 + kw + tig;
                bfr[nt][0] = Bw[bb];
                bfr[nt][1] = Bw[bb + 4];
            }
            #pragma unroll
            for (int mt = 0; mt < 2; mt++)
                #pragma unroll
                for (int nt = 0; nt < 2; nt++)
                    mma_bf16(acc[mt][nt], a[mt][0], a[mt][1], a[mt][2], a[mt][3],
                             bfr[nt][0], bfr[nt][1]);
        }
    }

    float gs = sigmoidf_(gate[0]);
    #pragma unroll
    for (int mt = 0; mt < 2; mt++)
        #pragma unroll
        for (int nt = 0; nt < 2; nt++)
            #pragma unroll
            for (int e = 0; e < 4; e++) {
                int r   = row0 + wm*32 + mt*16 + gid + (e >= 2 ? 8 : 0);
                int col = col0 + wn*16 + nt*8 + 2*tig + (e & 1);
                if (r >= NWIN) continue;
                float mg = sigmoidf_(acc[mt][nt][e] + b2[col]);
                float fused = gs*mg + (1.f - gs)*sigmoidf_(mg);
                int b  = r / 196, rr = r % 196;
                int hb = rr / 14, wb = rr % 14;
                int pp = col / Cn, c = col % Cn;
                int i = pp >> 2, j = pp & 3;
                int h = (hb*4 + i + 2) % Hn;
                int w = (wb*4 + j + 2) % Wn;
                size_t oi = ((size_t)(b*Hn + h)*Wn + w)*Cn + c;
                out[oi] = x[oi] + fused;
            }
}

// ---------------- launch ---------------------------------------------------
extern "C" void kernel_launch(void* const* d_in, const int* in_sizes, int n_in,
                              void* d_out, int out_size)
{
    const float* x      = (const float*)d_in[0];
    const float* gamma  = (const float*)d_in[1];
    const float* beta   = (const float*)d_in[2];
    const float* W1     = (const float*)d_in[3];
    const float* b1     = (const float*)d_in[4];
    const float* inc_w  = (const float*)d_in[5];
    const float* vote_w = (const float*)d_in[6];
    const float* W2     = (const float*)d_in[7];
    const float* b2     = (const float*)d_in[8];
    const float* gate   = (const float*)d_in[9];

    float* out = (float*)d_out;
    float* clauses_out = nullptr;
    float* summary_out = nullptr;
    if (out_size >= TOTAL_ELEMS) {
        clauses_out = out + OUT_ELEMS;
        summary_out = out + OUT_ELEMS + CL_ELEMS;
    }

    mega_pre_kernel<<<MEGA_BLOCKS, 256>>>(x, gamma, beta, inc_w, W1, W2);
    gemm1_tc<<<dim3(HID/64, (NWIN+63)/64, 2), 256>>>();
    clause4_kernel<<<NWIN/4, 256>>>(b1, vote_w, clauses_out, summary_out);
    gemm3_tc<<<dim3(IND/64, (NWIN+63)/64), 256>>>(x, b2, gate, out);
}